// round 17
// baseline (speedup 1.0000x reference)
#include <cuda_runtime.h>
#include <cstdint>

// Problem constants (fixed shapes per reference)
#define B_DIM 8
#define P_DIM 65536
#define C_DIM 32768
#define F_DIM 32
#define E_DIM 524288
#define N_CHUNK (C_DIM / 8)   // 4096 chunks of 8 channels

// Per-channel edge-range offsets (edge_channel is sorted)
__device__ int g_offs[C_DIM + 1];
// Gather scratch: agg[c][b*32+f]  (33.5 MB, mostly L2-resident)
__device__ __align__(16) float g_agg[(size_t)C_DIM * 256];
// Per-chunk completion flags (8 producer-warp arrivals each)
__device__ unsigned int g_flag[N_CHUNK];

// ---------- packed f32x2 helpers ----------
__device__ __forceinline__ unsigned long long ffma2(unsigned long long a,
                                                    unsigned long long b,
                                                    unsigned long long c) {
    unsigned long long d;
    asm("fma.rn.f32x2 %0, %1, %2, %3;" : "=l"(d) : "l"(a), "l"(b), "l"(c));
    return d;
}
__device__ __forceinline__ unsigned long long add2(unsigned long long a,
                                                   unsigned long long b) {
    unsigned long long d;
    asm("add.rn.f32x2 %0, %1, %2;" : "=l"(d) : "l"(a), "l"(b));
    return d;
}
__device__ __forceinline__ float hadd2(unsigned long long v) {
    float lo, hi;
    asm("mov.b64 {%0, %1}, %2;" : "=f"(lo), "=f"(hi) : "l"(v));
    return lo + hi;
}
__device__ __forceinline__ float fast_rcp(float x) {
    float r;
    asm("rcp.approx.f32 %0, %1;" : "=f"(r) : "f"(x));
    return r;
}
__device__ __forceinline__ float sigmoidf_fast(float x) {
    return fast_rcp(1.0f + __expf(-x));
}
__device__ __forceinline__ float tanhf_fast(float x) {
    return fmaf(2.0f, sigmoidf_fast(2.0f * x), -1.0f);
}

// ---------- kernel 1: segment offsets (boundary scatter) + flag reset ----------
__global__ void offsets_kernel(const int* __restrict__ ec) {
    int i = blockIdx.x * blockDim.x + threadIdx.x;
    if (i < N_CHUNK) g_flag[i] = 0u;          // reset pipeline flags every launch
    if (i >= E_DIM) return;
    int cur  = __ldg(ec + i);
    int prev = (i == 0) ? -1 : __ldg(ec + i - 1);
    for (int c = prev + 1; c <= cur; c++) g_offs[c] = i;  // lower_bound(ec, c) = i
    if (i == E_DIM - 1) {
        for (int c = cur + 1; c <= C_DIM; c++) g_offs[c] = E_DIM;
    }
}

// ---------- kernel 2: pipelined gather + GRU ----------
// Grid 8192: even bid = gather for chunk (bid>>1), odd bid = GRU for same
// chunk. Producer warps release via threadfence + atomicAdd (8 arrivals);
// consumer tid0 spins on ld.acquire.gpu with nanosleep backoff. Consumers
// prestage weights/bias/h before the wait. Producers of a chunk always have
// lower bids than its consumer -> dispatched no later -> no deadlock.
__global__ __launch_bounds__(256, 2)
void fused_kernel(const float* __restrict__ pf,   // path_features   [B,P,F]
                  const float* __restrict__ hf,   // channel_features[B,C,F]
                  const float* __restrict__ Wih,  // [3F,F]
                  const float* __restrict__ Whh,  // [3F,F]
                  const float* __restrict__ bih,  // [3F]
                  const float* __restrict__ bhh,  // [3F]
                  const int*   __restrict__ ep,   // edge_path [E]
                  float*       __restrict__ out)  // [B,C,F]
{
    __shared__ float4 sWih[8 * 96];
    __shared__ float4 sWhh[8 * 96];
    __shared__ float  sBias[128];
    __shared__ __align__(16) float sA[8][256];
    __shared__ __align__(16) float sH[8][256];

    const int chunk = blockIdx.x >> 1;
    const int role  = blockIdx.x & 1;
    const int tid   = threadIdx.x;
    const int w = tid >> 5, lane = tid & 31;
    const int bb = lane >> 3, q8 = lane & 7;

    if (role == 0) {
        // ================= gather: warp w -> channel chunk*8 + w =================
        const int c = chunk * 8 + w;
        unsigned long long aA0 = 0ull, aA1 = 0ull;   // batch bb
        unsigned long long aB0 = 0ull, aB1 = 0ull;   // batch bb+4
        const float* pfA = pf + (size_t)bb * (P_DIM * F_DIM) + q8 * 4;
        const float* pfB = pfA + (size_t)4 * (P_DIM * F_DIM);

        const int s0 = g_offs[c], e0 = g_offs[c + 1];
        int i = s0;
        for (; i + 8 <= e0; i += 8) {
            int p0 = __ldg(ep + i + 0);
            int p1 = __ldg(ep + i + 1);
            int p2 = __ldg(ep + i + 2);
            int p3 = __ldg(ep + i + 3);
            int p4 = __ldg(ep + i + 4);
            int p5 = __ldg(ep + i + 5);
            int p6 = __ldg(ep + i + 6);
            int p7 = __ldg(ep + i + 7);
            ulonglong2 vA0 = *(const ulonglong2*)(pfA + ((size_t)p0 << 5));
            ulonglong2 vB0 = *(const ulonglong2*)(pfB + ((size_t)p0 << 5));
            ulonglong2 vA1 = *(const ulonglong2*)(pfA + ((size_t)p1 << 5));
            ulonglong2 vB1 = *(const ulonglong2*)(pfB + ((size_t)p1 << 5));
            ulonglong2 vA2 = *(const ulonglong2*)(pfA + ((size_t)p2 << 5));
            ulonglong2 vB2 = *(const ulonglong2*)(pfB + ((size_t)p2 << 5));
            ulonglong2 vA3 = *(const ulonglong2*)(pfA + ((size_t)p3 << 5));
            ulonglong2 vB3 = *(const ulonglong2*)(pfB + ((size_t)p3 << 5));
            ulonglong2 vA4 = *(const ulonglong2*)(pfA + ((size_t)p4 << 5));
            ulonglong2 vB4 = *(const ulonglong2*)(pfB + ((size_t)p4 << 5));
            ulonglong2 vA5 = *(const ulonglong2*)(pfA + ((size_t)p5 << 5));
            ulonglong2 vB5 = *(const ulonglong2*)(pfB + ((size_t)p5 << 5));
            ulonglong2 vA6 = *(const ulonglong2*)(pfA + ((size_t)p6 << 5));
            ulonglong2 vB6 = *(const ulonglong2*)(pfB + ((size_t)p6 << 5));
            ulonglong2 vA7 = *(const ulonglong2*)(pfA + ((size_t)p7 << 5));
            ulonglong2 vB7 = *(const ulonglong2*)(pfB + ((size_t)p7 << 5));
            aA0 = add2(aA0, vA0.x); aA1 = add2(aA1, vA0.y);
            aB0 = add2(aB0, vB0.x); aB1 = add2(aB1, vB0.y);
            aA0 = add2(aA0, vA1.x); aA1 = add2(aA1, vA1.y);
            aB0 = add2(aB0, vB1.x); aB1 = add2(aB1, vB1.y);
            aA0 = add2(aA0, vA2.x); aA1 = add2(aA1, vA2.y);
            aB0 = add2(aB0, vB2.x); aB1 = add2(aB1, vB2.y);
            aA0 = add2(aA0, vA3.x); aA1 = add2(aA1, vA3.y);
            aB0 = add2(aB0, vB3.x); aB1 = add2(aB1, vB3.y);
            aA0 = add2(aA0, vA4.x); aA1 = add2(aA1, vA4.y);
            aB0 = add2(aB0, vB4.x); aB1 = add2(aB1, vB4.y);
            aA0 = add2(aA0, vA5.x); aA1 = add2(aA1, vA5.y);
            aB0 = add2(aB0, vB5.x); aB1 = add2(aB1, vB5.y);
            aA0 = add2(aA0, vA6.x); aA1 = add2(aA1, vA6.y);
            aB0 = add2(aB0, vB6.x); aB1 = add2(aB1, vB6.y);
            aA0 = add2(aA0, vA7.x); aA1 = add2(aA1, vA7.y);
            aB0 = add2(aB0, vB7.x); aB1 = add2(aB1, vB7.y);
        }
        for (; i < e0; i++) {
            int p = __ldg(ep + i);
            ulonglong2 vA = *(const ulonglong2*)(pfA + ((size_t)p << 5));
            ulonglong2 vB = *(const ulonglong2*)(pfB + ((size_t)p << 5));
            aA0 = add2(aA0, vA.x); aA1 = add2(aA1, vA.y);
            aB0 = add2(aB0, vB.x); aB1 = add2(aB1, vB.y);
        }

        float* dst = g_agg + (size_t)c * 256;
        ulonglong2 tA; tA.x = aA0; tA.y = aA1;
        ulonglong2 tB; tB.x = aB0; tB.y = aB1;
        *(ulonglong2*)(dst + bb * 32 + q8 * 4)       = tA;
        *(ulonglong2*)(dst + (bb + 4) * 32 + q8 * 4) = tB;

        __threadfence();                               // release this warp's STGs
        if (lane == 0) atomicAdd(&g_flag[chunk], 1u);  // 8 arrivals per chunk
        return;
    }

    // ================= GRU: prestage weights/bias/h, wait, GEMM =================
    for (int i = tid; i < 8 * 96; i += 256) {
        int fq = i / 96, row = i % 96;
        sWih[i] = __ldg((const float4*)(Wih + row * 32 + fq * 4));
        sWhh[i] = __ldg((const float4*)(Whh + row * 32 + fq * 4));
    }
    if (tid < 32) {
        sBias[tid]      = bih[tid]      + bhh[tid];       // r bias (combined)
        sBias[32 + tid] = bih[32 + tid] + bhh[32 + tid];  // z bias (combined)
        sBias[64 + tid] = bih[64 + tid];                  // n input bias
        sBias[96 + tid] = bhh[64 + tid];                  // n hidden bias (inside r*)
    }
    {
        const int c = chunk * 8 + w;
        const float* hA = hf + (size_t)bb * (C_DIM * F_DIM) + ((size_t)c << 5) + q8 * 4;
        const float* hB = hA + (size_t)4 * (C_DIM * F_DIM);
        ulonglong2 hvA = *(const ulonglong2*)hA;
        ulonglong2 hvB = *(const ulonglong2*)hB;
        *(ulonglong2*)&sH[w][bb * 32 + q8 * 4]       = hvA;
        *(ulonglong2*)&sH[w][(bb + 4) * 32 + q8 * 4] = hvB;
    }

    // Wait for this chunk's 8 producer warps
    if (tid == 0) {
        unsigned int v;
        do {
            asm volatile("ld.acquire.gpu.u32 %0, [%1];"
                         : "=r"(v) : "l"(&g_flag[chunk]) : "memory");
            if (v >= 8u) break;
            __nanosleep(64);
        } while (true);
    }
    __syncthreads();

    // Stage x from scratch (warp w stages channel w)
    {
        const int c = chunk * 8 + w;
        const float* src = g_agg + (size_t)c * 256;
        ulonglong2 xA = *(const ulonglong2*)(src + bb * 32 + q8 * 4);
        ulonglong2 xB = *(const ulonglong2*)(src + (bb + 4) * 32 + q8 * 4);
        *(ulonglong2*)&sA[w][bb * 32 + q8 * 4]       = xA;
        *(ulonglong2*)&sA[w][(bb + 4) * 32 + q8 * 4] = xB;
    }
    __syncthreads();

    // Warp-pair GEMM: pair p owns channels {2p, 2p+1}; parity = batch half
    const int p      = w >> 1;
    const int parity = w & 1;
    const int chA = 2 * p;
    const ulonglong2* WI = (const ulonglong2*)sWih;
    const ulonglong2* WH = (const ulonglong2*)sWhh;

    unsigned long long accr[2][4], accz[2][4], accxn[2][4], acchn[2][4];
#pragma unroll
    for (int cc = 0; cc < 2; cc++)
#pragma unroll
        for (int b = 0; b < 4; b++) {
            accr[cc][b] = 0ull; accz[cc][b] = 0ull;
            accxn[cc][b] = 0ull; acchn[cc][b] = 0ull;
        }

#pragma unroll
    for (int fq = 0; fq < 8; fq++) {
        ulonglong2 wir = WI[fq * 96 + lane];        // conflict-free LDS.128
        ulonglong2 wiz = WI[fq * 96 + 32 + lane];
        ulonglong2 win = WI[fq * 96 + 64 + lane];
        ulonglong2 whr = WH[fq * 96 + lane];
        ulonglong2 whz = WH[fq * 96 + 32 + lane];
        ulonglong2 whn = WH[fq * 96 + 64 + lane];
#pragma unroll
        for (int cc = 0; cc < 2; cc++) {
            const int ch = chA + cc;
#pragma unroll
            for (int b = 0; b < 4; b++) {
                const int row = (parity * 4 + b) * 32 + fq * 4;
                ulonglong2 a = *(const ulonglong2*)&sA[ch][row];  // broadcast
                ulonglong2 h = *(const ulonglong2*)&sH[ch][row];  // broadcast
                accr[cc][b]  = ffma2(a.y, wir.y, ffma2(a.x, wir.x, accr[cc][b]));
                accr[cc][b]  = ffma2(h.y, whr.y, ffma2(h.x, whr.x, accr[cc][b]));
                accz[cc][b]  = ffma2(a.y, wiz.y, ffma2(a.x, wiz.x, accz[cc][b]));
                accz[cc][b]  = ffma2(h.y, whz.y, ffma2(h.x, whz.x, accz[cc][b]));
                accxn[cc][b] = ffma2(a.y, win.y, ffma2(a.x, win.x, accxn[cc][b]));
                acchn[cc][b] = ffma2(h.y, whn.y, ffma2(h.x, whn.x, acchn[cc][b]));
            }
        }
    }

    const float br  = sBias[lane];
    const float bz  = sBias[32 + lane];
    const float bxn = sBias[64 + lane];
    const float bhn = sBias[96 + lane];
#pragma unroll
    for (int cc = 0; cc < 2; cc++) {
        const int ch = chA + cc;
        const int c  = chunk * 8 + ch;
        float* outp = out + ((size_t)c << 5) + lane;
#pragma unroll
        for (int b = 0; b < 4; b++) {
            const int gb = parity * 4 + b;
            float r  = sigmoidf_fast(hadd2(accr[cc][b]) + br);
            float z  = sigmoidf_fast(hadd2(accz[cc][b]) + bz);
            float n  = tanhf_fast(hadd2(accxn[cc][b]) + bxn + r * (hadd2(acchn[cc][b]) + bhn));
            float hv = sH[ch][gb * 32 + lane];
            outp[(size_t)gb * (C_DIM * F_DIM)] = (1.0f - z) * n + z * hv;  // coalesced STG
        }
    }
}

extern "C" void kernel_launch(void* const* d_in, const int* in_sizes, int n_in,
                              void* d_out, int out_size) {
    (void)in_sizes; (void)n_in; (void)out_size;
    const float* pf  = (const float*)d_in[0];
    const float* hf  = (const float*)d_in[1];
    const float* Wih = (const float*)d_in[2];
    const float* Whh = (const float*)d_in[3];
    const float* bih = (const float*)d_in[4];
    const float* bhh = (const float*)d_in[5];
    const int*   ep  = (const int*)d_in[6];
    const int*   ec  = (const int*)d_in[7];
    float* out = (float*)d_out;

    offsets_kernel<<<E_DIM / 256, 256>>>(ec);
    fused_kernel<<<2 * N_CHUNK, 256>>>(pf, hf, Wih, Whh, bih, bhh, ep, out);
}